// round 10
// baseline (speedup 1.0000x reference)
#include <cuda_runtime.h>
#include <cuda_fp16.h>
#include <cuda_pipeline.h>
#include <mma.h>

using namespace nvcuda;

#define N_DIM 2048
#define BATCH 8192

// Scratch (allocation banned -> __device__ globals). All operands fp16.
__device__ __align__(1024) __half g_Sh [N_DIM * N_DIM];
__device__ __align__(1024) __half g_S2h[N_DIM * N_DIM];
__device__ __align__(1024) __half g_S3h[N_DIM * N_DIM];
__device__ __align__(1024) __half g_S4h[N_DIM * N_DIM];
__device__ __align__(1024) __half g_Uh [N_DIM * N_DIM];
__device__ __align__(1024) __half g_Rh [N_DIM * N_DIM];
__device__ __align__(1024) __half g_Xh [BATCH * N_DIM];

// Build antisymmetric S (as fp16) from strict-upper-triangle flat vector.
__global__ void build_S_kernel(const float* __restrict__ S_flat) {
    int idx = blockIdx.x * blockDim.x + threadIdx.x;
    if (idx >= N_DIM * N_DIM) return;
    int i = idx / N_DIM;
    int j = idx % N_DIM;
    float v = 0.0f;
    if (i < j) {
        int f = i * (2 * N_DIM - i - 1) / 2 + (j - i - 1);
        v = S_flat[f];
    } else if (i > j) {
        int f = j * (2 * N_DIM - j - 1) / 2 + (i - j - 1);
        v = -S_flat[f];
    }
    g_Sh[idx] = __float2half_rn(v);
}

// Convert X to fp16 once.
__global__ void convert_X_kernel(const float* __restrict__ X) {
    int f = blockIdx.x * blockDim.x + threadIdx.x;
    if (f >= BATCH * N_DIM / 4) return;
    float4 v = reinterpret_cast<const float4*>(X)[f];
    __half2 h0 = __floats2half2_rn(v.x, v.y);
    __half2 h1 = __floats2half2_rn(v.z, v.w);
    uint2 p;
    p.x = *reinterpret_cast<unsigned*>(&h0);
    p.y = *reinterpret_cast<unsigned*>(&h1);
    reinterpret_cast<uint2*>(g_Xh)[f] = p;
}

// ---------------------------------------------------------------------------
// FP16 wmma GEMM, fp32 accumulate, warp tile 64x64, CTA tile 128x256.
//   res = alpha*(A@B) + idcoef*I + e0*E0 + e1*E1 + e2*E2 + e3*E3
//   Ch = half(res) (if non-null);  Cf = res (if non-null)
// A: MxK, B: KxN, row-major fp16. M mult of 128, N mult of 256, K mult of 32.
// ---------------------------------------------------------------------------
#define BM 128
#define BN 256
#define BK 32
#define A_LD 40        // 32 + 8 halves pad
#define B_LD 264       // 256 + 8 halves pad
#define STAGES 3
#define A_STG (BM * A_LD)          // 5120 halves
#define B_STG (BK * B_LD)          // 8448 halves
#define B_BASE (STAGES * A_STG)    // halves
#define EPI_LD 132                 // floats (128 + 4 pad)
#define SMEM_BYTES (STAGES * (A_STG + B_STG) * 2)   // 81408; epi needs 67584 < this

__global__ __launch_bounds__(256, 1) void hgemm_kernel(
    const __half* __restrict__ A, const __half* __restrict__ B,
    __half* __restrict__ Ch, float* __restrict__ Cf,
    int M, int N, int K,
    float alpha, float idcoef,
    const __half* __restrict__ E0, float e0,
    const __half* __restrict__ E1, float e1,
    const __half* __restrict__ E2, float e2,
    const __half* __restrict__ E3, float e3)
{
    extern __shared__ char smraw[];
    __half* smh = reinterpret_cast<__half*>(smraw);
    float*  smf = reinterpret_cast<float*>(smraw);

    const int tid = threadIdx.x;
    const int warpId = tid >> 5;
    const int rowBase = blockIdx.y * BM;
    const int colBase = blockIdx.x * BN;

    // warp grid 2(M) x 4(N); warp tile 64x64
    const int warpM0 = (warpId >> 2) * 64;
    const int warpN0 = (warpId & 3) * 64;

    // global->smem load mapping (8-half = 16B chunks)
    // A tile: 128x32 halves -> 512 chunks (2/thread): row = ch>>2, col = (ch&3)*8
    // B tile:  32x256 halves -> 1024 chunks (4/thread): row = ch>>5, col = (ch&31)*8
    const int nsteps = K / BK;

    auto issue = [&](int step) {
        int buf = step % STAGES;
        size_t k0 = (size_t)step * BK;
        __half* As = smh + buf * A_STG;
        __half* Bs = smh + B_BASE + buf * B_STG;
#pragma unroll
        for (int i = 0; i < 2; ++i) {
            int ch = tid + i * 256;
            int r = ch >> 2, c = (ch & 3) << 3;
            __pipeline_memcpy_async(As + r * A_LD + c,
                A + (size_t)(rowBase + r) * K + k0 + c, 16);
        }
#pragma unroll
        for (int i = 0; i < 4; ++i) {
            int ch = tid + i * 256;
            int r = ch >> 5, c = (ch & 31) << 3;
            __pipeline_memcpy_async(Bs + r * B_LD + c,
                B + (size_t)(k0 + r) * N + colBase + c, 16);
        }
        __pipeline_commit();
    };

    wmma::fragment<wmma::accumulator, 16, 16, 16, float> acc[4][4];
#pragma unroll
    for (int i = 0; i < 4; ++i)
#pragma unroll
        for (int j = 0; j < 4; ++j)
            wmma::fill_fragment(acc[i][j], 0.0f);

    issue(0);
    issue(1);

    for (int step = 0; step < nsteps; ++step) {
        if (step + 2 < nsteps)      { issue(step + 2); __pipeline_wait_prior(2); }
        else if (step + 1 < nsteps) { __pipeline_wait_prior(1); }
        else                        { __pipeline_wait_prior(0); }
        __syncthreads();

        const __half* As = smh + (step % STAGES) * A_STG;
        const __half* Bs = smh + B_BASE + (step % STAGES) * B_STG;

#pragma unroll
        for (int kk = 0; kk < BK; kk += 16) {
            wmma::fragment<wmma::matrix_a, 16, 16, 16, __half, wmma::row_major> afrag[4];
#pragma unroll
            for (int i = 0; i < 4; ++i)
                wmma::load_matrix_sync(afrag[i], As + (warpM0 + 16 * i) * A_LD + kk, A_LD);
#pragma unroll
            for (int j = 0; j < 4; ++j) {
                wmma::fragment<wmma::matrix_b, 16, 16, 16, __half, wmma::row_major> bfrag;
                wmma::load_matrix_sync(bfrag, Bs + kk * B_LD + warpN0 + 16 * j, B_LD);
#pragma unroll
                for (int i = 0; i < 4; ++i)
                    wmma::mma_sync(acc[i][j], afrag[i], bfrag, acc[i][j]);
            }
        }
        __syncthreads();
    }

    // scale once
#pragma unroll
    for (int i = 0; i < 4; ++i)
#pragma unroll
        for (int j = 0; j < 4; ++j)
#pragma unroll
            for (int t = 0; t < acc[i][j].num_elements; ++t)
                acc[i][j].x[t] *= alpha;

    // ---- epilogue: two column-half passes through a 128x128 fp32 smem tile ----
#pragma unroll
    for (int h = 0; h < 2; ++h) {
        __syncthreads();
        if (((warpId & 3) >> 1) == h) {
            int colLoc = (warpId & 1) * 64;   // warpN0 - 128*h
#pragma unroll
            for (int i = 0; i < 4; ++i)
#pragma unroll
                for (int j = 0; j < 4; ++j)
                    wmma::store_matrix_sync(
                        smf + (warpM0 + 16 * i) * EPI_LD + colLoc + 16 * j,
                        acc[i][j], EPI_LD, wmma::mem_row_major);
        }
        __syncthreads();

#pragma unroll 4
        for (int g = 0; g < 16; ++g) {
            int e4 = tid + g * 256;          // float4 id within 128x128 half
            int rr = e4 >> 5;
            int c4 = (e4 & 31) << 2;
            float4 v = *reinterpret_cast<const float4*>(smf + rr * EPI_LD + c4);
            size_t gr = rowBase + rr;
            size_t gc = colBase + h * 128 + c4;
            size_t gi = gr * N + gc;

            auto addE = [&](const __half* E, float e) {
                uint2 p = *reinterpret_cast<const uint2*>(E + gi);
                float2 f0 = __half22float2(*reinterpret_cast<__half2*>(&p.x));
                float2 f1 = __half22float2(*reinterpret_cast<__half2*>(&p.y));
                v.x += e * f0.x; v.y += e * f0.y; v.z += e * f1.x; v.w += e * f1.y;
            };
            if (E0) addE(E0, e0);
            if (E1) addE(E1, e1);
            if (E2) addE(E2, e2);
            if (E3) addE(E3, e3);

            if (idcoef != 0.0f && gr >= gc && gr < gc + 4) {
                if      (gr == gc)     v.x += idcoef;
                else if (gr == gc + 1) v.y += idcoef;
                else if (gr == gc + 2) v.z += idcoef;
                else                   v.w += idcoef;
            }

            if (Ch) {
                __half2 h0 = __floats2half2_rn(v.x, v.y);
                __half2 h1 = __floats2half2_rn(v.z, v.w);
                uint2 p;
                p.x = *reinterpret_cast<unsigned*>(&h0);
                p.y = *reinterpret_cast<unsigned*>(&h1);
                *reinterpret_cast<uint2*>(Ch + gi) = p;
            }
            if (Cf) *reinterpret_cast<float4*>(Cf + gi) = v;
        }
    }
}

extern "C" void kernel_launch(void* const* d_in, const int* in_sizes, int n_in,
                              void* d_out, int out_size) {
    const float* X      = (const float*)d_in[0];   // [BATCH, N]
    const float* S_flat = (const float*)d_in[1];   // [N*(N-1)/2]
    float* Y = (float*)d_out;                      // [BATCH, N]

    __half *S, *S2, *S3, *S4, *U, *R, *Xh;
    cudaGetSymbolAddress((void**)&S,  g_Sh);
    cudaGetSymbolAddress((void**)&S2, g_S2h);
    cudaGetSymbolAddress((void**)&S3, g_S3h);
    cudaGetSymbolAddress((void**)&S4, g_S4h);
    cudaGetSymbolAddress((void**)&U,  g_Uh);
    cudaGetSymbolAddress((void**)&R,  g_Rh);
    cudaGetSymbolAddress((void**)&Xh, g_Xh);

    cudaFuncSetAttribute(hgemm_kernel,
                         cudaFuncAttributeMaxDynamicSharedMemorySize, SMEM_BYTES);

    // Taylor coefficients 1/k!
    const float c1 = 1.0f;
    const float c2 = 1.0f / 2.0f;
    const float c3 = 1.0f / 6.0f;
    const float c4 = 1.0f / 24.0f;
    const float c5 = 1.0f / 120.0f;
    const float c6 = 1.0f / 720.0f;
    const float c7 = 1.0f / 5040.0f;
    const float c8 = 1.0f / 40320.0f;
    const float c9 = 1.0f / 362880.0f;

    build_S_kernel<<<(N_DIM * N_DIM + 255) / 256, 256>>>(S_flat);
    convert_X_kernel<<<(BATCH * N_DIM / 4 + 255) / 256, 256>>>(X);

    dim3 gridSq(N_DIM / BN, N_DIM / BM);   // (8, 16)

    // Powers
    hgemm_kernel<<<gridSq, 256, SMEM_BYTES>>>(S,  S,  S2, nullptr, N_DIM, N_DIM, N_DIM,
        1.0f, 0.0f, nullptr,0, nullptr,0, nullptr,0, nullptr,0);
    hgemm_kernel<<<gridSq, 256, SMEM_BYTES>>>(S2, S,  S3, nullptr, N_DIM, N_DIM, N_DIM,
        1.0f, 0.0f, nullptr,0, nullptr,0, nullptr,0, nullptr,0);
    hgemm_kernel<<<gridSq, 256, SMEM_BYTES>>>(S2, S2, S4, nullptr, N_DIM, N_DIM, N_DIM,
        1.0f, 0.0f, nullptr,0, nullptr,0, nullptr,0, nullptr,0);

    // Paterson–Stockmeyer combine:
    // U = c9*(S4@S) + c8*S4 + c7*S3 + c6*S2 + c5*S + c4*I
    hgemm_kernel<<<gridSq, 256, SMEM_BYTES>>>(S4, S, U, nullptr, N_DIM, N_DIM, N_DIM,
        c9, c4, S4, c8, S3, c7, S2, c6, S, c5);
    // R = (S4@U) + c3*S3 + c2*S2 + c1*S + I
    hgemm_kernel<<<gridSq, 256, SMEM_BYTES>>>(S4, U, R, nullptr, N_DIM, N_DIM, N_DIM,
        1.0f, 1.0f, S3, c3, S2, c2, S, c1, nullptr, 0);

    // Y = X @ R   (fp32 out)
    dim3 gridY(N_DIM / BN, BATCH / BM);    // (8, 64)
    hgemm_kernel<<<gridY, 256, SMEM_BYTES>>>(Xh, R, nullptr, Y, BATCH, N_DIM, N_DIM,
        1.0f, 0.0f, nullptr,0, nullptr,0, nullptr,0, nullptr,0);
}

// round 11
// speedup vs baseline: 1.4979x; 1.4979x over previous
#include <cuda_runtime.h>
#include <cuda_fp16.h>
#include <cuda_pipeline.h>
#include <mma.h>

using namespace nvcuda;

#define N_DIM 2048
#define BATCH 8192
#define NT (N_DIM / 128)          // 16 tile-rows
#define NTRI (NT * (NT + 1) / 2)  // 136 upper-triangle tiles

// Scratch (allocation banned -> __device__ globals). fp16 operands.
__device__ __align__(1024) __half g_Sh [N_DIM * N_DIM];
__device__ __align__(1024) __half g_Wh [N_DIM * N_DIM];   // S^2
__device__ __align__(1024) __half g_P2h[N_DIM * N_DIM];   // W^2
__device__ __align__(1024) __half g_P3h[N_DIM * N_DIM];   // W^3
__device__ __align__(1024) __half g_P4h[N_DIM * N_DIM];   // W^4
__device__ __align__(1024) __half g_Eh [N_DIM * N_DIM];   // even part
__device__ __align__(1024) __half g_Gh [N_DIM * N_DIM];   // odd inner poly
__device__ __align__(1024) __half g_Rh [N_DIM * N_DIM];   // exp(S)
__device__ __align__(1024) __half g_Xh [BATCH * N_DIM];

// ---------------- prep kernels ----------------
__global__ void build_S_kernel(const float* __restrict__ S_flat) {
    int idx = blockIdx.x * blockDim.x + threadIdx.x;
    if (idx >= N_DIM * N_DIM) return;
    int i = idx / N_DIM;
    int j = idx % N_DIM;
    float v = 0.0f;
    if (i < j) {
        int f = i * (2 * N_DIM - i - 1) / 2 + (j - i - 1);
        v = S_flat[f];
    } else if (i > j) {
        int f = j * (2 * N_DIM - j - 1) / 2 + (i - j - 1);
        v = -S_flat[f];
    }
    g_Sh[idx] = __float2half_rn(v);
}

__global__ void convert_X_kernel(const float* __restrict__ X) {
    int f = blockIdx.x * blockDim.x + threadIdx.x;
    if (f >= BATCH * N_DIM / 4) return;
    float4 v = reinterpret_cast<const float4*>(X)[f];
    __half2 h0 = __floats2half2_rn(v.x, v.y);
    __half2 h1 = __floats2half2_rn(v.z, v.w);
    uint2 p;
    p.x = *reinterpret_cast<unsigned*>(&h0);
    p.y = *reinterpret_cast<unsigned*>(&h1);
    reinterpret_cast<uint2*>(g_Xh)[f] = p;
}

// E = I + c2 W + c4 W2 + c6 W3 + c8 W4 ; G = c1 I + c3 W + c5 W2 + c7 W3 + c9 W4
__global__ void build_EG_kernel() {
    const float c1 = 1.0f, c2 = 0.5f, c3 = 1.0f / 6.0f, c4 = 1.0f / 24.0f;
    const float c5 = 1.0f / 120.0f, c6 = 1.0f / 720.0f, c7 = 1.0f / 5040.0f;
    const float c8 = 1.0f / 40320.0f, c9 = 1.0f / 362880.0f;
    int idx2 = blockIdx.x * blockDim.x + threadIdx.x;
    if (idx2 >= N_DIM * N_DIM / 2) return;
    int row = idx2 / (N_DIM / 2);
    int c0 = (idx2 % (N_DIM / 2)) * 2;
    float2 w  = __half22float2(reinterpret_cast<const __half2*>(g_Wh )[idx2]);
    float2 p2 = __half22float2(reinterpret_cast<const __half2*>(g_P2h)[idx2]);
    float2 p3 = __half22float2(reinterpret_cast<const __half2*>(g_P3h)[idx2]);
    float2 p4 = __half22float2(reinterpret_cast<const __half2*>(g_P4h)[idx2]);
    float ex = c2 * w.x + c4 * p2.x + c6 * p3.x + c8 * p4.x;
    float ey = c2 * w.y + c4 * p2.y + c6 * p3.y + c8 * p4.y;
    float gx = c3 * w.x + c5 * p2.x + c7 * p3.x + c9 * p4.x;
    float gy = c3 * w.y + c5 * p2.y + c7 * p3.y + c9 * p4.y;
    if (row == c0)     { ex += 1.0f; gx += c1; }
    if (row == c0 + 1) { ey += 1.0f; gy += c1; }
    reinterpret_cast<__half2*>(g_Eh)[idx2] = __floats2half2_rn(ex, ey);
    reinterpret_cast<__half2*>(g_Gh)[idx2] = __floats2half2_rn(gx, gy);
}

// ---------------------------------------------------------------------------
// Shared GEMM config (round-4 proven operating point)
// ---------------------------------------------------------------------------
#define BM 128
#define BN 128
#define BK 32
#define A_LD 40        // 32 + 8 halves pad
#define B_LD 136       // 128 + 8 halves pad
#define STAGES 3
#define A_STG (BM * A_LD)          // 5120 halves
#define B_STG (BK * B_LD)          // 4352 halves
#define B_BASE (STAGES * A_STG)
#define EPI_LD 132                 // floats
#define EPI_SZ (128 * EPI_LD)      // 16896 floats = 67584 B
#define SMEM_FULL 67584            // max(pipeline 56832, epi 67584)
#define SMEM_TRI  (2 * EPI_SZ * 4) // 135168 (pipeline 56832 fits underneath)
#define NSTEPS (N_DIM / BK)        // 64

// ---------------------------------------------------------------------------
// Triangle GEMM: C = alpha*(A@B) for upper-triangle tiles (bi<=bj);
// mirror tile (bj,bi) written as msign * transpose (+ extra E at mirror coords).
// Optional variant select for merged launches (blockIdx.x >= NTRI -> B1/C1).
// All matrices N_DIM x N_DIM row-major fp16.
// ---------------------------------------------------------------------------
__global__ __launch_bounds__(256) void hgemm_tri(
    const __half* __restrict__ A,
    const __half* __restrict__ B0, const __half* __restrict__ B1,
    __half* __restrict__ C0, __half* __restrict__ C1,
    float alpha, float msign,
    const __half* __restrict__ E0p, float e0)
{
    extern __shared__ char smraw[];
    __half* smh = reinterpret_cast<__half*>(smraw);
    float*  epi  = reinterpret_cast<float*>(smraw);
    float*  epiT = reinterpret_cast<float*>(smraw) + EPI_SZ;

    // decode triangle index (and merged-launch variant)
    int t = blockIdx.x;
    int variant = 0;
    if (t >= NTRI) { t -= NTRI; variant = 1; }
    int bi = 0;
    while (t >= NT - bi) { t -= NT - bi; ++bi; }
    int bj = bi + t;

    const __half* B  = variant ? B1 : B0;
    __half*       Ch = variant ? C1 : C0;

    const int tid = threadIdx.x;
    const int warpId = tid >> 5;
    const int rowBase = bi * BM;
    const int colBase = bj * BN;

    const int warpM0 = (warpId >> 1) * 32;
    const int warpN0 = (warpId & 1) * 64;

    const int aRow0 = tid >> 2,          aCol0 = (tid & 3) << 3;
    const int aRow1 = (tid + 256) >> 2,  aCol1 = aCol0;
    const int bRow0 = tid >> 4,          bCol0 = (tid & 15) << 3;
    const int bRow1 = (tid >> 4) + 16,   bCol1 = bCol0;

    const __half* aP0 = A + (size_t)(rowBase + aRow0) * N_DIM + aCol0;
    const __half* aP1 = A + (size_t)(rowBase + aRow1) * N_DIM + aCol1;
    const __half* bP0 = B + (size_t)bRow0 * N_DIM + colBase + bCol0;
    const __half* bP1 = B + (size_t)bRow1 * N_DIM + colBase + bCol1;

    auto issue = [&](int step) {
        int buf = step % STAGES;
        size_t ka = (size_t)step * BK;
        __half* As = smh + buf * A_STG;
        __half* Bs = smh + B_BASE + buf * B_STG;
        __pipeline_memcpy_async(As + aRow0 * A_LD + aCol0, aP0 + ka, 16);
        __pipeline_memcpy_async(As + aRow1 * A_LD + aCol1, aP1 + ka, 16);
        __pipeline_memcpy_async(Bs + bRow0 * B_LD + bCol0, bP0 + ka * N_DIM, 16);
        __pipeline_memcpy_async(Bs + bRow1 * B_LD + bCol1, bP1 + ka * N_DIM, 16);
        __pipeline_commit();
    };

    wmma::fragment<wmma::accumulator, 16, 16, 16, float> acc[2][4];
#pragma unroll
    for (int i = 0; i < 2; ++i)
#pragma unroll
        for (int j = 0; j < 4; ++j)
            wmma::fill_fragment(acc[i][j], 0.0f);

    issue(0);
    issue(1);

    for (int step = 0; step < NSTEPS; ++step) {
        if (step + 2 < NSTEPS)      { issue(step + 2); __pipeline_wait_prior(2); }
        else if (step + 1 < NSTEPS) { __pipeline_wait_prior(1); }
        else                        { __pipeline_wait_prior(0); }
        __syncthreads();

        const __half* As = smh + (step % STAGES) * A_STG;
        const __half* Bs = smh + B_BASE + (step % STAGES) * B_STG;

#pragma unroll
        for (int kk = 0; kk < BK; kk += 16) {
            wmma::fragment<wmma::matrix_a, 16, 16, 16, __half, wmma::row_major> afrag[2];
            wmma::fragment<wmma::matrix_b, 16, 16, 16, __half, wmma::row_major> bfrag[4];
#pragma unroll
            for (int i = 0; i < 2; ++i)
                wmma::load_matrix_sync(afrag[i], As + (warpM0 + 16 * i) * A_LD + kk, A_LD);
#pragma unroll
            for (int j = 0; j < 4; ++j)
                wmma::load_matrix_sync(bfrag[j], Bs + kk * B_LD + warpN0 + 16 * j, B_LD);
#pragma unroll
            for (int i = 0; i < 2; ++i)
#pragma unroll
                for (int j = 0; j < 4; ++j)
                    wmma::mma_sync(acc[i][j], afrag[i], bfrag[j], acc[i][j]);
        }
        __syncthreads();
    }

    // ---- epilogue: scale, stage direct (row-major) AND transposed (col-major)
    __syncthreads();
#pragma unroll
    for (int i = 0; i < 2; ++i)
#pragma unroll
        for (int j = 0; j < 4; ++j) {
#pragma unroll
            for (int tt = 0; tt < acc[i][j].num_elements; ++tt)
                acc[i][j].x[tt] *= alpha;
            wmma::store_matrix_sync(epi + (warpM0 + 16 * i) * EPI_LD + warpN0 + 16 * j,
                                    acc[i][j], EPI_LD, wmma::mem_row_major);
            // epiT holds D^T (row-major): elem(r,c) of D -> epiT[c*EPI_LD + r]
            wmma::store_matrix_sync(epiT + (warpN0 + 16 * j) * EPI_LD + warpM0 + 16 * i,
                                    acc[i][j], EPI_LD, wmma::mem_col_major);
        }
    __syncthreads();

    // direct tile (bi,bj)
#pragma unroll 4
    for (int g = 0; g < 16; ++g) {
        int e4 = tid + g * 256;
        int rr = e4 >> 5;
        int c4 = (e4 & 31) << 2;
        float4 v = *reinterpret_cast<const float4*>(epi + rr * EPI_LD + c4);
        size_t gi = (size_t)(rowBase + rr) * N_DIM + colBase + c4;
        if (E0p) {
            uint2 p = *reinterpret_cast<const uint2*>(E0p + gi);
            float2 f0 = __half22float2(*reinterpret_cast<__half2*>(&p.x));
            float2 f1 = __half22float2(*reinterpret_cast<__half2*>(&p.y));
            v.x += e0 * f0.x; v.y += e0 * f0.y; v.z += e0 * f1.x; v.w += e0 * f1.y;
        }
        __half2 h0 = __floats2half2_rn(v.x, v.y);
        __half2 h1 = __floats2half2_rn(v.z, v.w);
        uint2 p;
        p.x = *reinterpret_cast<unsigned*>(&h0);
        p.y = *reinterpret_cast<unsigned*>(&h1);
        *reinterpret_cast<uint2*>(Ch + gi) = p;
    }

    // mirror tile (bj,bi): msign * D^T (+ extra at mirror coords)
    if (bi != bj) {
#pragma unroll 4
        for (int g = 0; g < 16; ++g) {
            int e4 = tid + g * 256;
            int rr = e4 >> 5;
            int c4 = (e4 & 31) << 2;
            float4 v = *reinterpret_cast<const float4*>(epiT + rr * EPI_LD + c4);
            v.x *= msign; v.y *= msign; v.z *= msign; v.w *= msign;
            size_t gi = (size_t)(colBase + rr) * N_DIM + rowBase + c4;
            if (E0p) {
                uint2 p = *reinterpret_cast<const uint2*>(E0p + gi);
                float2 f0 = __half22float2(*reinterpret_cast<__half2*>(&p.x));
                float2 f1 = __half22float2(*reinterpret_cast<__half2*>(&p.y));
                v.x += e0 * f0.x; v.y += e0 * f0.y; v.z += e0 * f1.x; v.w += e0 * f1.y;
            }
            __half2 h0 = __floats2half2_rn(v.x, v.y);
            __half2 h1 = __floats2half2_rn(v.z, v.w);
            uint2 p;
            p.x = *reinterpret_cast<unsigned*>(&h0);
            p.y = *reinterpret_cast<unsigned*>(&h1);
            *reinterpret_cast<uint2*>(Ch + gi) = p;
        }
    }
}

// ---------------------------------------------------------------------------
// Full GEMM for Y = A(MxK) @ B(KxN), fp32 out. K=N=N_DIM fixed.
// ---------------------------------------------------------------------------
__global__ __launch_bounds__(256) void hgemm_full(
    const __half* __restrict__ A, const __half* __restrict__ B,
    float* __restrict__ Cf)
{
    extern __shared__ char smraw[];
    __half* smh = reinterpret_cast<__half*>(smraw);
    float*  smf = reinterpret_cast<float*>(smraw);

    const int tid = threadIdx.x;
    const int warpId = tid >> 5;
    const int rowBase = blockIdx.y * BM;
    const int colBase = blockIdx.x * BN;

    const int warpM0 = (warpId >> 1) * 32;
    const int warpN0 = (warpId & 1) * 64;

    const int aRow0 = tid >> 2,          aCol0 = (tid & 3) << 3;
    const int aRow1 = (tid + 256) >> 2,  aCol1 = aCol0;
    const int bRow0 = tid >> 4,          bCol0 = (tid & 15) << 3;
    const int bRow1 = (tid >> 4) + 16,   bCol1 = bCol0;

    const __half* aP0 = A + (size_t)(rowBase + aRow0) * N_DIM + aCol0;
    const __half* aP1 = A + (size_t)(rowBase + aRow1) * N_DIM + aCol1;
    const __half* bP0 = B + (size_t)bRow0 * N_DIM + colBase + bCol0;
    const __half* bP1 = B + (size_t)bRow1 * N_DIM + colBase + bCol1;

    auto issue = [&](int step) {
        int buf = step % STAGES;
        size_t ka = (size_t)step * BK;
        __half* As = smh + buf * A_STG;
        __half* Bs = smh + B_BASE + buf * B_STG;
        __pipeline_memcpy_async(As + aRow0 * A_LD + aCol0, aP0 + ka, 16);
        __pipeline_memcpy_async(As + aRow1 * A_LD + aCol1, aP1 + ka, 16);
        __pipeline_memcpy_async(Bs + bRow0 * B_LD + bCol0, bP0 + ka * N_DIM, 16);
        __pipeline_memcpy_async(Bs + bRow1 * B_LD + bCol1, bP1 + ka * N_DIM, 16);
        __pipeline_commit();
    };

    wmma::fragment<wmma::accumulator, 16, 16, 16, float> acc[2][4];
#pragma unroll
    for (int i = 0; i < 2; ++i)
#pragma unroll
        for (int j = 0; j < 4; ++j)
            wmma::fill_fragment(acc[i][j], 0.0f);

    issue(0);
    issue(1);

    for (int step = 0; step < NSTEPS; ++step) {
        if (step + 2 < NSTEPS)      { issue(step + 2); __pipeline_wait_prior(2); }
        else if (step + 1 < NSTEPS) { __pipeline_wait_prior(1); }
        else                        { __pipeline_wait_prior(0); }
        __syncthreads();

        const __half* As = smh + (step % STAGES) * A_STG;
        const __half* Bs = smh + B_BASE + (step % STAGES) * B_STG;

#pragma unroll
        for (int kk = 0; kk < BK; kk += 16) {
            wmma::fragment<wmma::matrix_a, 16, 16, 16, __half, wmma::row_major> afrag[2];
            wmma::fragment<wmma::matrix_b, 16, 16, 16, __half, wmma::row_major> bfrag[4];
#pragma unroll
            for (int i = 0; i < 2; ++i)
                wmma::load_matrix_sync(afrag[i], As + (warpM0 + 16 * i) * A_LD + kk, A_LD);
#pragma unroll
            for (int j = 0; j < 4; ++j)
                wmma::load_matrix_sync(bfrag[j], Bs + kk * B_LD + warpN0 + 16 * j, B_LD);
#pragma unroll
            for (int i = 0; i < 2; ++i)
#pragma unroll
                for (int j = 0; j < 4; ++j)
                    wmma::mma_sync(acc[i][j], afrag[i], bfrag[j], acc[i][j]);
        }
        __syncthreads();
    }

    __syncthreads();
#pragma unroll
    for (int i = 0; i < 2; ++i)
#pragma unroll
        for (int j = 0; j < 4; ++j)
            wmma::store_matrix_sync(smf + (warpM0 + 16 * i) * EPI_LD + warpN0 + 16 * j,
                                    acc[i][j], EPI_LD, wmma::mem_row_major);
    __syncthreads();

#pragma unroll 4
    for (int g = 0; g < 16; ++g) {
        int e4 = tid + g * 256;
        int rr = e4 >> 5;
        int c4 = (e4 & 31) << 2;
        float4 v = *reinterpret_cast<const float4*>(smf + rr * EPI_LD + c4);
        size_t gi = (size_t)(rowBase + rr) * N_DIM + colBase + c4;
        *reinterpret_cast<float4*>(Cf + gi) = v;
    }
}

extern "C" void kernel_launch(void* const* d_in, const int* in_sizes, int n_in,
                              void* d_out, int out_size) {
    const float* X      = (const float*)d_in[0];   // [BATCH, N]
    const float* S_flat = (const float*)d_in[1];   // [N*(N-1)/2]
    float* Y = (float*)d_out;                      // [BATCH, N]

    __half *S, *W, *P2, *P3, *P4, *E, *G, *R, *Xh;
    cudaGetSymbolAddress((void**)&S,  g_Sh);
    cudaGetSymbolAddress((void**)&W,  g_Wh);
    cudaGetSymbolAddress((void**)&P2, g_P2h);
    cudaGetSymbolAddress((void**)&P3, g_P3h);
    cudaGetSymbolAddress((void**)&P4, g_P4h);
    cudaGetSymbolAddress((void**)&E,  g_Eh);
    cudaGetSymbolAddress((void**)&G,  g_Gh);
    cudaGetSymbolAddress((void**)&R,  g_Rh);
    cudaGetSymbolAddress((void**)&Xh, g_Xh);

    cudaFuncSetAttribute(hgemm_tri,
                         cudaFuncAttributeMaxDynamicSharedMemorySize, SMEM_TRI);
    cudaFuncSetAttribute(hgemm_full,
                         cudaFuncAttributeMaxDynamicSharedMemorySize, SMEM_FULL);

    build_S_kernel<<<(N_DIM * N_DIM + 255) / 256, 256>>>(S_flat);
    convert_X_kernel<<<(BATCH * N_DIM / 4 + 255) / 256, 256>>>(X);

    // W = S @ S  (symmetric)
    hgemm_tri<<<NTRI, 256, SMEM_TRI>>>(S, S, nullptr, W, nullptr,
                                       1.0f, 1.0f, nullptr, 0.0f);
    // P2 = W @ W  (symmetric)
    hgemm_tri<<<NTRI, 256, SMEM_TRI>>>(W, W, nullptr, P2, nullptr,
                                       1.0f, 1.0f, nullptr, 0.0f);
    // merged: P3 = P2 @ W, P4 = P2 @ P2  (both symmetric)
    hgemm_tri<<<2 * NTRI, 256, SMEM_TRI>>>(P2, W, P2, P3, P4,
                                           1.0f, 1.0f, nullptr, 0.0f);
    // E, G elementwise polynomials in W
    build_EG_kernel<<<(N_DIM * N_DIM / 2 + 255) / 256, 256>>>();
    // R = S @ G + E  (S@G antisymmetric -> msign = -1; E symmetric extra)
    hgemm_tri<<<NTRI, 256, SMEM_TRI>>>(S, G, nullptr, R, nullptr,
                                       1.0f, -1.0f, E, 1.0f);
    // Y = X @ R
    dim3 gY(N_DIM / BN, BATCH / BM);   // (16, 64)
    hgemm_full<<<gY, 256, SMEM_FULL>>>(Xh, R, Y);
}

// round 13
// speedup vs baseline: 1.5499x; 1.0347x over previous
#include <cuda_runtime.h>
#include <cuda_fp16.h>
#include <cuda_pipeline.h>
#include <mma.h>

using namespace nvcuda;

#define N_DIM 2048
#define BATCH 8192
#define NT (N_DIM / 128)          // 16 tile-rows
#define NTRI (NT * (NT + 1) / 2)  // 136 upper-triangle tiles

// Scratch (allocation banned -> __device__ globals). fp16 operands.
__device__ __align__(1024) __half g_Sh [N_DIM * N_DIM];
__device__ __align__(1024) __half g_Wh [N_DIM * N_DIM];   // S^2
__device__ __align__(1024) __half g_P2h[N_DIM * N_DIM];   // W^2
__device__ __align__(1024) __half g_P3h[N_DIM * N_DIM];   // W^3
__device__ __align__(1024) __half g_P4h[N_DIM * N_DIM];   // W^4
__device__ __align__(1024) __half g_Eh [N_DIM * N_DIM];   // even part
__device__ __align__(1024) __half g_Gh [N_DIM * N_DIM];   // odd inner poly
__device__ __align__(1024) __half g_Rh [N_DIM * N_DIM];   // exp(S)
__device__ __align__(1024) __half g_Xh [BATCH * N_DIM];

// ---------------- prep kernels ----------------
__global__ void build_S_kernel(const float* __restrict__ S_flat) {
    int idx = blockIdx.x * blockDim.x + threadIdx.x;
    if (idx >= N_DIM * N_DIM) return;
    int i = idx / N_DIM;
    int j = idx % N_DIM;
    float v = 0.0f;
    if (i < j) {
        int f = i * (2 * N_DIM - i - 1) / 2 + (j - i - 1);
        v = S_flat[f];
    } else if (i > j) {
        int f = j * (2 * N_DIM - j - 1) / 2 + (i - j - 1);
        v = -S_flat[f];
    }
    g_Sh[idx] = __float2half_rn(v);
}

__global__ void convert_X_kernel(const float* __restrict__ X) {
    int f = blockIdx.x * blockDim.x + threadIdx.x;
    if (f >= BATCH * N_DIM / 4) return;
    float4 v = reinterpret_cast<const float4*>(X)[f];
    __half2 h0 = __floats2half2_rn(v.x, v.y);
    __half2 h1 = __floats2half2_rn(v.z, v.w);
    uint2 p;
    p.x = *reinterpret_cast<unsigned*>(&h0);
    p.y = *reinterpret_cast<unsigned*>(&h1);
    reinterpret_cast<uint2*>(g_Xh)[f] = p;
}

// E = I + c2 W + c4 W2 + c6 W3 + c8 W4 ; G = c1 I + c3 W + c5 W2 + c7 W3 + c9 W4
__global__ void build_EG_kernel() {
    const float c1 = 1.0f, c2 = 0.5f, c3 = 1.0f / 6.0f, c4 = 1.0f / 24.0f;
    const float c5 = 1.0f / 120.0f, c6 = 1.0f / 720.0f, c7 = 1.0f / 5040.0f;
    const float c8 = 1.0f / 40320.0f, c9 = 1.0f / 362880.0f;
    int idx2 = blockIdx.x * blockDim.x + threadIdx.x;
    if (idx2 >= N_DIM * N_DIM / 2) return;
    int row = idx2 / (N_DIM / 2);
    int c0 = (idx2 % (N_DIM / 2)) * 2;
    float2 w  = __half22float2(reinterpret_cast<const __half2*>(g_Wh )[idx2]);
    float2 p2 = __half22float2(reinterpret_cast<const __half2*>(g_P2h)[idx2]);
    float2 p3 = __half22float2(reinterpret_cast<const __half2*>(g_P3h)[idx2]);
    float2 p4 = __half22float2(reinterpret_cast<const __half2*>(g_P4h)[idx2]);
    float ex = c2 * w.x + c4 * p2.x + c6 * p3.x + c8 * p4.x;
    float ey = c2 * w.y + c4 * p2.y + c6 * p3.y + c8 * p4.y;
    float gx = c3 * w.x + c5 * p2.x + c7 * p3.x + c9 * p4.x;
    float gy = c3 * w.y + c5 * p2.y + c7 * p3.y + c9 * p4.y;
    if (row == c0)     { ex += 1.0f; gx += c1; }
    if (row == c0 + 1) { ey += 1.0f; gy += c1; }
    reinterpret_cast<__half2*>(g_Eh)[idx2] = __floats2half2_rn(ex, ey);
    reinterpret_cast<__half2*>(g_Gh)[idx2] = __floats2half2_rn(gx, gy);
}

// ---------------------------------------------------------------------------
// Shared GEMM config
// ---------------------------------------------------------------------------
#define BM 128
#define BN 128
#define BK 32
#define A_LD 40        // 32 + 8 halves pad
#define B_LD 136       // 128 + 8 halves pad
#define STAGES 4
#define A_STG (BM * A_LD)          // 5120 halves
#define B_STG (BK * B_LD)          // 4352 halves
#define B_BASE (STAGES * A_STG)
#define EPI_LD 132                 // floats
#define EPI_SZ (128 * EPI_LD)      // floats
#define SMEM_GEMM (STAGES * (A_STG + B_STG) * 2)   // 75776 B; epi 67584 fits inside
#define NSTEPS (N_DIM / BK)        // 64
#define PERSIST_CTAS 296           // 148 SMs x 2 CTA/SM
#define YTILES ((BATCH / BM) * (NT))  // 64 x 16 = 1024

// ---------------------------------------------------------------------------
// Triangle GEMM: C = alpha*(A@B) for upper-triangle tiles (bi<=bj);
// mirror tile (bj,bi) written as msign * transpose (+ extra E at both coords).
// Optional variant select for merged launches (blockIdx.x >= NTRI -> B1/C1).
// ---------------------------------------------------------------------------
__global__ __launch_bounds__(256) void hgemm_tri(
    const __half* __restrict__ A,
    const __half* __restrict__ B0, const __half* __restrict__ B1,
    __half* __restrict__ C0, __half* __restrict__ C1,
    float alpha, float msign,
    const __half* __restrict__ E0p, float e0)
{
    extern __shared__ char smraw[];
    __half* smh = reinterpret_cast<__half*>(smraw);
    float*  epi = reinterpret_cast<float*>(smraw);

    int t = blockIdx.x;
    int variant = 0;
    if (t >= NTRI) { t -= NTRI; variant = 1; }
    int bi = 0;
    while (t >= NT - bi) { t -= NT - bi; ++bi; }
    int bj = bi + t;

    const __half* B  = variant ? B1 : B0;
    __half*       Ch = variant ? C1 : C0;

    const int tid = threadIdx.x;
    const int warpId = tid >> 5;
    const int rowBase = bi * BM;
    const int colBase = bj * BN;

    const int warpM0 = (warpId >> 1) * 32;
    const int warpN0 = (warpId & 1) * 64;

    const int aRow0 = tid >> 2,          aCol0 = (tid & 3) << 3;
    const int aRow1 = (tid + 256) >> 2,  aCol1 = aCol0;
    const int bRow0 = tid >> 4,          bCol0 = (tid & 15) << 3;
    const int bRow1 = (tid >> 4) + 16,   bCol1 = bCol0;

    const __half* aP0 = A + (size_t)(rowBase + aRow0) * N_DIM + aCol0;
    const __half* aP1 = A + (size_t)(rowBase + aRow1) * N_DIM + aCol1;
    const __half* bP0 = B + (size_t)bRow0 * N_DIM + colBase + bCol0;
    const __half* bP1 = B + (size_t)bRow1 * N_DIM + colBase + bCol1;

    auto issue = [&](int step) {
        int buf = step % STAGES;
        size_t ka = (size_t)step * BK;
        __half* As = smh + buf * A_STG;
        __half* Bs = smh + B_BASE + buf * B_STG;
        __pipeline_memcpy_async(As + aRow0 * A_LD + aCol0, aP0 + ka, 16);
        __pipeline_memcpy_async(As + aRow1 * A_LD + aCol1, aP1 + ka, 16);
        __pipeline_memcpy_async(Bs + bRow0 * B_LD + bCol0, bP0 + ka * N_DIM, 16);
        __pipeline_memcpy_async(Bs + bRow1 * B_LD + bCol1, bP1 + ka * N_DIM, 16);
        __pipeline_commit();
    };

    wmma::fragment<wmma::accumulator, 16, 16, 16, float> acc[2][4];
#pragma unroll
    for (int i = 0; i < 2; ++i)
#pragma unroll
        for (int j = 0; j < 4; ++j)
            wmma::fill_fragment(acc[i][j], 0.0f);

    issue(0); issue(1); issue(2);

    for (int step = 0; step < NSTEPS; ++step) {
        if (step + 3 < NSTEPS) issue(step + 3);
        const int rem = NSTEPS - 1 - step;
        if (rem >= 3)      __pipeline_wait_prior(3);
        else if (rem == 2) __pipeline_wait_prior(2);
        else if (rem == 1) __pipeline_wait_prior(1);
        else               __pipeline_wait_prior(0);
        __syncthreads();

        const __half* As = smh + (step % STAGES) * A_STG;
        const __half* Bs = smh + B_BASE + (step % STAGES) * B_STG;

#pragma unroll
        for (int kk = 0; kk < BK; kk += 16) {
            wmma::fragment<wmma::matrix_a, 16, 16, 16, __half, wmma::row_major> afrag[2];
            wmma::fragment<wmma::matrix_b, 16, 16, 16, __half, wmma::row_major> bfrag[4];
#pragma unroll
            for (int i = 0; i < 2; ++i)
                wmma::load_matrix_sync(afrag[i], As + (warpM0 + 16 * i) * A_LD + kk, A_LD);
#pragma unroll
            for (int j = 0; j < 4; ++j)
                wmma::load_matrix_sync(bfrag[j], Bs + kk * B_LD + warpN0 + 16 * j, B_LD);
#pragma unroll
            for (int i = 0; i < 2; ++i)
#pragma unroll
                for (int j = 0; j < 4; ++j)
                    wmma::mma_sync(acc[i][j], afrag[i], bfrag[j], acc[i][j]);
        }
        __syncthreads();
    }

    // scale once
#pragma unroll
    for (int i = 0; i < 2; ++i)
#pragma unroll
        for (int j = 0; j < 4; ++j)
#pragma unroll
            for (int tt = 0; tt < acc[i][j].num_elements; ++tt)
                acc[i][j].x[tt] *= alpha;

    auto write_tile = [&](int rB, int cB, bool doSign) {
#pragma unroll 4
        for (int g = 0; g < 16; ++g) {
            int e4 = tid + g * 256;
            int rr = e4 >> 5;
            int c4 = (e4 & 31) << 2;
            float4 v = *reinterpret_cast<const float4*>(epi + rr * EPI_LD + c4);
            if (doSign) { v.x *= msign; v.y *= msign; v.z *= msign; v.w *= msign; }
            size_t gi = (size_t)(rB + rr) * N_DIM + cB + c4;
            if (E0p) {
                uint2 p = *reinterpret_cast<const uint2*>(E0p + gi);
                float2 f0 = __half22float2(*reinterpret_cast<__half2*>(&p.x));
                float2 f1 = __half22float2(*reinterpret_cast<__half2*>(&p.y));
                v.x += e0 * f0.x; v.y += e0 * f0.y; v.z += e0 * f1.x; v.w += e0 * f1.y;
            }
            __half2 h0 = __floats2half2_rn(v.x, v.y);
            __half2 h1 = __floats2half2_rn(v.z, v.w);
            uint2 p;
            p.x = *reinterpret_cast<unsigned*>(&h0);
            p.y = *reinterpret_cast<unsigned*>(&h1);
            *reinterpret_cast<uint2*>(Ch + gi) = p;
        }
    };

    // pass 1: direct tile (bi,bj)
    __syncthreads();
#pragma unroll
    for (int i = 0; i < 2; ++i)
#pragma unroll
        for (int j = 0; j < 4; ++j)
            wmma::store_matrix_sync(epi + (warpM0 + 16 * i) * EPI_LD + warpN0 + 16 * j,
                                    acc[i][j], EPI_LD, wmma::mem_row_major);
    __syncthreads();
    write_tile(rowBase, colBase, false);

    // pass 2: mirror tile (bj,bi) = msign * D^T
    if (bi != bj) {
        __syncthreads();
#pragma unroll
        for (int i = 0; i < 2; ++i)
#pragma unroll
            for (int j = 0; j < 4; ++j)
                wmma::store_matrix_sync(epi + (warpN0 + 16 * j) * EPI_LD + warpM0 + 16 * i,
                                        acc[i][j], EPI_LD, wmma::mem_col_major);
        __syncthreads();
        write_tile(colBase, rowBase, true);
    }
}

// ---------------------------------------------------------------------------
// Persistent full GEMM: Y(BATCH x N_DIM) = Xh @ R, fp32 out.
// grid = PERSIST_CTAS; each CTA loops over tiles.
// ---------------------------------------------------------------------------
__global__ __launch_bounds__(256) void hgemm_yfull(
    const __half* __restrict__ A, const __half* __restrict__ B,
    float* __restrict__ Cf)
{
    extern __shared__ char smraw[];
    __half* smh = reinterpret_cast<__half*>(smraw);
    float*  smf = reinterpret_cast<float*>(smraw);

    const int tid = threadIdx.x;
    const int warpId = tid >> 5;
    const int warpM0 = (warpId >> 1) * 32;
    const int warpN0 = (warpId & 1) * 64;

    const int aRow0 = tid >> 2,          aCol0 = (tid & 3) << 3;
    const int aRow1 = (tid + 256) >> 2,  aCol1 = aCol0;
    const int bRow0 = tid >> 4,          bCol0 = (tid & 15) << 3;
    const int bRow1 = (tid >> 4) + 16,   bCol1 = bCol0;

    for (int tile = blockIdx.x; tile < YTILES; tile += gridDim.x) {
        const int rowBase = (tile >> 4) * BM;
        const int colBase = (tile & 15) * BN;

        const __half* aP0 = A + (size_t)(rowBase + aRow0) * N_DIM + aCol0;
        const __half* aP1 = A + (size_t)(rowBase + aRow1) * N_DIM + aCol1;
        const __half* bP0 = B + (size_t)bRow0 * N_DIM + colBase + bCol0;
        const __half* bP1 = B + (size_t)bRow1 * N_DIM + colBase + bCol1;

        auto issue = [&](int step) {
            int buf = step % STAGES;
            size_t ka = (size_t)step * BK;
            __half* As = smh + buf * A_STG;
            __half* Bs = smh + B_BASE + buf * B_STG;
            __pipeline_memcpy_async(As + aRow0 * A_LD + aCol0, aP0 + ka, 16);
            __pipeline_memcpy_async(As + aRow1 * A_LD + aCol1, aP1 + ka, 16);
            __pipeline_memcpy_async(Bs + bRow0 * B_LD + bCol0, bP0 + ka * N_DIM, 16);
            __pipeline_memcpy_async(Bs + bRow1 * B_LD + bCol1, bP1 + ka * N_DIM, 16);
            __pipeline_commit();
        };

        wmma::fragment<wmma::accumulator, 16, 16, 16, float> acc[2][4];
#pragma unroll
        for (int i = 0; i < 2; ++i)
#pragma unroll
            for (int j = 0; j < 4; ++j)
                wmma::fill_fragment(acc[i][j], 0.0f);

        issue(0); issue(1); issue(2);

        for (int step = 0; step < NSTEPS; ++step) {
            if (step + 3 < NSTEPS) issue(step + 3);
            const int rem = NSTEPS - 1 - step;
            if (rem >= 3)      __pipeline_wait_prior(3);
            else if (rem == 2) __pipeline_wait_prior(2);
            else if (rem == 1) __pipeline_wait_prior(1);
            else               __pipeline_wait_prior(0);
            __syncthreads();

            const __half* As = smh + (step % STAGES) * A_STG;
            const __half* Bs = smh + B_BASE + (step % STAGES) * B_STG;

#pragma unroll
            for (int kk = 0; kk < BK; kk += 16) {
                wmma::fragment<wmma::matrix_a, 16, 16, 16, __half, wmma::row_major> afrag[2];
                wmma::fragment<wmma::matrix_b, 16, 16, 16, __half, wmma::row_major> bfrag[4];
#pragma unroll
                for (int i = 0; i < 2; ++i)
                    wmma::load_matrix_sync(afrag[i], As + (warpM0 + 16 * i) * A_LD + kk, A_LD);
#pragma unroll
                for (int j = 0; j < 4; ++j)
                    wmma::load_matrix_sync(bfrag[j], Bs + kk * B_LD + warpN0 + 16 * j, B_LD);
#pragma unroll
                for (int i = 0; i < 2; ++i)
#pragma unroll
                    for (int j = 0; j < 4; ++j)
                        wmma::mma_sync(acc[i][j], afrag[i], bfrag[j], acc[i][j]);
            }
            __syncthreads();
        }

        // epilogue
#pragma unroll
        for (int i = 0; i < 2; ++i)
#pragma unroll
            for (int j = 0; j < 4; ++j)
                wmma::store_matrix_sync(smf + (warpM0 + 16 * i) * EPI_LD + warpN0 + 16 * j,
                                        acc[i][j], EPI_LD, wmma::mem_row_major);
        __syncthreads();

#pragma unroll 4
        for (int g = 0; g < 16; ++g) {
            int e4 = tid + g * 256;
            int rr = e4 >> 5;
            int c4 = (e4 & 31) << 2;
            float4 v = *reinterpret_cast<const float4*>(smf + rr * EPI_LD + c4);
            size_t gi = (size_t)(rowBase + rr) * N_DIM + colBase + c4;
            *reinterpret_cast<float4*>(Cf + gi) = v;
        }
        __syncthreads();   // smem safe for next tile's cp.async
    }
}

extern "C" void kernel_launch(void* const* d_in, const int* in_sizes, int n_in,
                              void* d_out, int out_size) {
    const float* X      = (const float*)d_in[0];   // [BATCH, N]
    const float* S_flat = (const float*)d_in[1];   // [N*(N-1)/2]
    float* Y = (float*)d_out;                      // [BATCH, N]

    __half *S, *W, *P2, *P3, *P4, *E, *G, *R, *Xh;
    cudaGetSymbolAddress((void**)&S,  g_Sh);
    cudaGetSymbolAddress((void**)&W,  g_Wh);
    cudaGetSymbolAddress((void**)&P2, g_P2h);
    cudaGetSymbolAddress((void**)&P3, g_P3h);
    cudaGetSymbolAddress((void**)&P4, g_P4h);
    cudaGetSymbolAddress((void**)&E,  g_Eh);
    cudaGetSymbolAddress((void**)&G,  g_Gh);
    cudaGetSymbolAddress((void**)&R,  g_Rh);
    cudaGetSymbolAddress((void**)&Xh, g_Xh);

    cudaFuncSetAttribute(hgemm_tri,
                         cudaFuncAttributeMaxDynamicSharedMemorySize, SMEM_GEMM);
    cudaFuncSetAttribute(hgemm_yfull,
                         cudaFuncAttributeMaxDynamicSharedMemorySize, SMEM_GEMM);

    build_S_kernel<<<(N_DIM * N_DIM + 255) / 256, 256>>>(S_flat);
    convert_X_kernel<<<(BATCH * N_DIM / 4 + 255) / 256, 256>>>(X);

    // W = S @ S  (symmetric)
    hgemm_tri<<<NTRI, 256, SMEM_GEMM>>>(S, S, nullptr, W, nullptr,
                                        1.0f, 1.0f, nullptr, 0.0f);
    // P2 = W @ W  (symmetric)
    hgemm_tri<<<NTRI, 256, SMEM_GEMM>>>(W, W, nullptr, P2, nullptr,
                                        1.0f, 1.0f, nullptr, 0.0f);
    // merged: P3 = P2 @ W, P4 = P2 @ P2  (both symmetric) — now one wave
    hgemm_tri<<<2 * NTRI, 256, SMEM_GEMM>>>(P2, W, P2, P3, P4,
                                            1.0f, 1.0f, nullptr, 0.0f);
    // E, G elementwise polynomials in W
    build_EG_kernel<<<(N_DIM * N_DIM / 2 + 255) / 256, 256>>>();
    // R = S @ G + E  (S@G antisymmetric -> msign = -1; E symmetric extra)
    hgemm_tri<<<NTRI, 256, SMEM_GEMM>>>(S, G, nullptr, R, nullptr,
                                        1.0f, -1.0f, E, 1.0f);
    // Y = X @ R  (persistent)
    hgemm_yfull<<<PERSIST_CTAS, 256, SMEM_GEMM>>>(Xh, R, Y);
}

// round 14
// speedup vs baseline: 1.5840x; 1.0220x over previous
#include <cuda_runtime.h>
#include <cuda_fp16.h>
#include <cuda_pipeline.h>
#include <cstdint>

#define N_DIM 2048
#define BATCH 8192
#define NT (N_DIM / 128)          // 16 tile-rows
#define NTRI (NT * (NT + 1) / 2)  // 136 upper-triangle tiles

// Scratch (allocation banned -> __device__ globals). fp16 operands.
__device__ __align__(1024) __half g_Sh [N_DIM * N_DIM];
__device__ __align__(1024) __half g_Wh [N_DIM * N_DIM];   // S^2
__device__ __align__(1024) __half g_P2h[N_DIM * N_DIM];   // W^2
__device__ __align__(1024) __half g_P3h[N_DIM * N_DIM];   // W^3
__device__ __align__(1024) __half g_P4h[N_DIM * N_DIM];   // W^4
__device__ __align__(1024) __half g_Eh [N_DIM * N_DIM];   // even part
__device__ __align__(1024) __half g_Gh [N_DIM * N_DIM];   // odd inner poly
__device__ __align__(1024) __half g_Rh [N_DIM * N_DIM];   // exp(S)
__device__ __align__(1024) __half g_Xh [BATCH * N_DIM];

// ---------------- PTX helpers ----------------
__device__ __forceinline__ uint32_t smem_u32(const void* p) {
    uint32_t a;
    asm("{ .reg .u64 t; cvta.to.shared.u64 t, %1; cvt.u32.u64 %0, t; }"
        : "=r"(a) : "l"(p));
    return a;
}
__device__ __forceinline__ void ldsm4(uint32_t* r, uint32_t addr) {
    asm volatile("ldmatrix.sync.aligned.m8n8.x4.shared.b16 {%0,%1,%2,%3}, [%4];"
        : "=r"(r[0]), "=r"(r[1]), "=r"(r[2]), "=r"(r[3]) : "r"(addr));
}
__device__ __forceinline__ void ldsm4t(uint32_t* r, uint32_t addr) {
    asm volatile("ldmatrix.sync.aligned.m8n8.x4.trans.shared.b16 {%0,%1,%2,%3}, [%4];"
        : "=r"(r[0]), "=r"(r[1]), "=r"(r[2]), "=r"(r[3]) : "r"(addr));
}
__device__ __forceinline__ void mma16816(float* c, const uint32_t* a, const uint32_t* b) {
    asm volatile(
        "mma.sync.aligned.m16n8k16.row.col.f32.f16.f16.f32 "
        "{%0,%1,%2,%3}, {%4,%5,%6,%7}, {%8,%9}, {%0,%1,%2,%3};"
        : "+f"(c[0]), "+f"(c[1]), "+f"(c[2]), "+f"(c[3])
        : "r"(a[0]), "r"(a[1]), "r"(a[2]), "r"(a[3]), "r"(b[0]), "r"(b[1]));
}

// ---------------- prep kernels ----------------
__global__ void build_S_kernel(const float* __restrict__ S_flat) {
    int idx = blockIdx.x * blockDim.x + threadIdx.x;
    if (idx >= N_DIM * N_DIM) return;
    int i = idx / N_DIM;
    int j = idx % N_DIM;
    float v = 0.0f;
    if (i < j) {
        int f = i * (2 * N_DIM - i - 1) / 2 + (j - i - 1);
        v = S_flat[f];
    } else if (i > j) {
        int f = j * (2 * N_DIM - j - 1) / 2 + (i - j - 1);
        v = -S_flat[f];
    }
    g_Sh[idx] = __float2half_rn(v);
}

__global__ void convert_X_kernel(const float* __restrict__ X) {
    int f = blockIdx.x * blockDim.x + threadIdx.x;
    if (f >= BATCH * N_DIM / 4) return;
    float4 v = reinterpret_cast<const float4*>(X)[f];
    __half2 h0 = __floats2half2_rn(v.x, v.y);
    __half2 h1 = __floats2half2_rn(v.z, v.w);
    uint2 p;
    p.x = *reinterpret_cast<unsigned*>(&h0);
    p.y = *reinterpret_cast<unsigned*>(&h1);
    reinterpret_cast<uint2*>(g_Xh)[f] = p;
}

// E = I + c2 W + c4 W2 + c6 W3 + c8 W4 ; G = c1 I + c3 W + c5 W2 + c7 W3 + c9 W4
__global__ void build_EG_kernel() {
    const float c1 = 1.0f, c2 = 0.5f, c3 = 1.0f / 6.0f, c4 = 1.0f / 24.0f;
    const float c5 = 1.0f / 120.0f, c6 = 1.0f / 720.0f, c7 = 1.0f / 5040.0f;
    const float c8 = 1.0f / 40320.0f, c9 = 1.0f / 362880.0f;
    int idx2 = blockIdx.x * blockDim.x + threadIdx.x;
    if (idx2 >= N_DIM * N_DIM / 2) return;
    int row = idx2 / (N_DIM / 2);
    int c0 = (idx2 % (N_DIM / 2)) * 2;
    float2 w  = __half22float2(reinterpret_cast<const __half2*>(g_Wh )[idx2]);
    float2 p2 = __half22float2(reinterpret_cast<const __half2*>(g_P2h)[idx2]);
    float2 p3 = __half22float2(reinterpret_cast<const __half2*>(g_P3h)[idx2]);
    float2 p4 = __half22float2(reinterpret_cast<const __half2*>(g_P4h)[idx2]);
    float ex = c2 * w.x + c4 * p2.x + c6 * p3.x + c8 * p4.x;
    float ey = c2 * w.y + c4 * p2.y + c6 * p3.y + c8 * p4.y;
    float gx = c3 * w.x + c5 * p2.x + c7 * p3.x + c9 * p4.x;
    float gy = c3 * w.y + c5 * p2.y + c7 * p3.y + c9 * p4.y;
    if (row == c0)     { ex += 1.0f; gx += c1; }
    if (row == c0 + 1) { ey += 1.0f; gy += c1; }
    reinterpret_cast<__half2*>(g_Eh)[idx2] = __floats2half2_rn(ex, ey);
    reinterpret_cast<__half2*>(g_Gh)[idx2] = __floats2half2_rn(gx, gy);
}

// ---------------------------------------------------------------------------
// GEMM config
// ---------------------------------------------------------------------------
#define BM 128
#define BN 128
#define BK 32
#define A_LD 40        // halves (32 + 8 pad); row stride 80 B (16B-multiple)
#define B_LD 136       // halves (128 + 8 pad); row stride 272 B (16B-multiple)
#define STAGES 4
#define A_STG (BM * A_LD)          // halves
#define B_STG (BK * B_LD)          // halves
#define B_BASE (STAGES * A_STG)    // halves
#define EPI_LD 132                 // floats
#define SMEM_GEMM (STAGES * (A_STG + B_STG) * 2)   // 75776 B
#define NSTEPS (N_DIM / BK)        // 64
#define PERSIST_CTAS 296
#define YTILES ((BATCH / BM) * NT) // 1024

// ---------------------------------------------------------------------------
// Triangle GEMM: C = alpha*(A@B) for upper-triangle tiles (bi<=bj);
// mirror tile (bj,bi) = msign * transpose (+ E extra at both coords).
// variant select for merged launches (blockIdx.x >= NTRI -> B1/C1).
// ---------------------------------------------------------------------------
__global__ __launch_bounds__(256, 2) void hgemm_tri(
    const __half* __restrict__ A,
    const __half* __restrict__ B0, const __half* __restrict__ B1,
    __half* __restrict__ C0, __half* __restrict__ C1,
    float alpha, float msign,
    const __half* __restrict__ E0p, float e0)
{
    extern __shared__ char smraw[];
    __half* smh = reinterpret_cast<__half*>(smraw);
    float*  epi = reinterpret_cast<float*>(smraw);
    const uint32_t smb = smem_u32(smraw);

    int t = blockIdx.x;
    int variant = 0;
    if (t >= NTRI) { t -= NTRI; variant = 1; }
    int bi = 0;
    while (t >= NT - bi) { t -= NT - bi; ++bi; }
    int bj = bi + t;

    const __half* B  = variant ? B1 : B0;
    __half*       Ch = variant ? C1 : C0;

    const int tid = threadIdx.x;
    const int warpId = tid >> 5;
    const int lid = tid & 31;
    const int rowBase = bi * BM;
    const int colBase = bj * BN;

    const int warpM0 = (warpId >> 1) * 32;
    const int warpN0 = (warpId & 1) * 64;

    // cp.async mapping
    const int aRow0 = tid >> 2,          aCol0 = (tid & 3) << 3;
    const int aRow1 = (tid + 256) >> 2,  aCol1 = aCol0;
    const int bRow0 = tid >> 4,          bCol0 = (tid & 15) << 3;
    const int bRow1 = (tid >> 4) + 16,   bCol1 = bCol0;

    const __half* aP0 = A + (size_t)(rowBase + aRow0) * N_DIM + aCol0;
    const __half* aP1 = A + (size_t)(rowBase + aRow1) * N_DIM + aCol1;
    const __half* bP0 = B + (size_t)bRow0 * N_DIM + colBase + bCol0;
    const __half* bP1 = B + (size_t)bRow1 * N_DIM + colBase + bCol1;

    auto issue = [&](int step) {
        int buf = step % STAGES;
        size_t ka = (size_t)step * BK;
        __half* As = smh + buf * A_STG;
        __half* Bs = smh + B_BASE + buf * B_STG;
        __pipeline_memcpy_async(As + aRow0 * A_LD + aCol0, aP0 + ka, 16);
        __pipeline_memcpy_async(As + aRow1 * A_LD + aCol1, aP1 + ka, 16);
        __pipeline_memcpy_async(Bs + bRow0 * B_LD + bCol0, bP0 + ka * N_DIM, 16);
        __pipeline_memcpy_async(Bs + bRow1 * B_LD + bCol1, bP1 + ka * N_DIM, 16);
        __pipeline_commit();
    };

    // ldmatrix lane-fixed byte offsets
    const uint32_t aFix = (uint32_t)(warpM0 + (lid & 15)) * (A_LD * 2)
                        + ((lid >> 4) << 3) * 2;
    const uint32_t bFix = (uint32_t)(lid & 15) * (B_LD * 2)
                        + (uint32_t)(warpN0 + ((lid >> 4) << 3)) * 2;

    float acc[2][8][4];
#pragma unroll
    for (int i = 0; i < 2; ++i)
#pragma unroll
        for (int j = 0; j < 8; ++j)
#pragma unroll
            for (int q = 0; q < 4; ++q) acc[i][j][q] = 0.0f;

    issue(0); issue(1); issue(2);

    for (int step = 0; step < NSTEPS; ++step) {
        if (step + 3 < NSTEPS) issue(step + 3);
        const int rem = NSTEPS - 1 - step;
        if (rem >= 3)      __pipeline_wait_prior(3);
        else if (rem == 2) __pipeline_wait_prior(2);
        else if (rem == 1) __pipeline_wait_prior(1);
        else               __pipeline_wait_prior(0);
        __syncthreads();

        const int buf = step % STAGES;
        const uint32_t aS = smb + buf * (A_STG * 2) + aFix;
        const uint32_t bS = smb + (B_BASE + buf * B_STG) * 2 + bFix;

#pragma unroll
        for (int kk = 0; kk < BK; kk += 16) {
            uint32_t ar[2][4], br[4][4];
            ldsm4(ar[0], aS + kk * 2);
            ldsm4(ar[1], aS + kk * 2 + 16 * (A_LD * 2));
#pragma unroll
            for (int nj = 0; nj < 4; ++nj)
                ldsm4t(br[nj], bS + kk * (B_LD * 2) + nj * 32);
#pragma unroll
            for (int mt = 0; mt < 2; ++mt)
#pragma unroll
                for (int nj = 0; nj < 4; ++nj) {
                    mma16816(acc[mt][nj * 2 + 0], ar[mt], br[nj]);
                    mma16816(acc[mt][nj * 2 + 1], ar[mt], br[nj] + 2);
                }
        }
        __syncthreads();
    }

    // scale once
#pragma unroll
    for (int i = 0; i < 2; ++i)
#pragma unroll
        for (int j = 0; j < 8; ++j)
#pragma unroll
            for (int q = 0; q < 4; ++q) acc[i][j][q] *= alpha;

    const int lr = lid >> 2;          // 0..7
    const int lc = (lid & 3) << 1;    // 0,2,4,6

    auto write_tile = [&](int rB, int cB, bool doSign) {
#pragma unroll 4
        for (int g = 0; g < 16; ++g) {
            int e4 = tid + g * 256;
            int rr = e4 >> 5;
            int c4 = (e4 & 31) << 2;
            float4 v = *reinterpret_cast<const float4*>(epi + rr * EPI_LD + c4);
            if (doSign) { v.x *= msign; v.y *= msign; v.z *= msign; v.w *= msign; }
            size_t gi = (size_t)(rB + rr) * N_DIM + cB + c4;
            if (E0p) {
                uint2 p = *reinterpret_cast<const uint2*>(E0p + gi);
                float2 f0 = __half22float2(*reinterpret_cast<__half2*>(&p.x));
                float2 f1 = __half22float2(*reinterpret_cast<__half2*>(&p.y));
                v.x += e0 * f0.x; v.y += e0 * f0.y; v.z += e0 * f1.x; v.w += e0 * f1.y;
            }
            __half2 h0 = __floats2half2_rn(v.x, v.y);
            __half2 h1 = __floats2half2_rn(v.z, v.w);
            uint2 p;
            p.x = *reinterpret_cast<unsigned*>(&h0);
            p.y = *reinterpret_cast<unsigned*>(&h1);
            *reinterpret_cast<uint2*>(Ch + gi) = p;
        }
    };

    // pass 1: direct tile (row-major acc layout of m16n8k16)
    __syncthreads();
#pragma unroll
    for (int mt = 0; mt < 2; ++mt)
#pragma unroll
        for (int nt = 0; nt < 8; ++nt) {
            int r0 = warpM0 + mt * 16 + lr;
            int c0 = warpN0 + nt * 8 + lc;
            epi[r0 * EPI_LD + c0]           = acc[mt][nt][0];
            epi[r0 * EPI_LD + c0 + 1]       = acc[mt][nt][1];
            epi[(r0 + 8) * EPI_LD + c0]     = acc[mt][nt][2];
            epi[(r0 + 8) * EPI_LD + c0 + 1] = acc[mt][nt][3];
        }
    __syncthreads();
    write_tile(rowBase, colBase, false);

    // pass 2: mirror tile (bj,bi) = msign * D^T
    if (bi != bj) {
        __syncthreads();
#pragma unroll
        for (int mt = 0; mt < 2; ++mt)
#pragma unroll
            for (int nt = 0; nt < 8; ++nt) {
                int r0 = warpM0 + mt * 16 + lr;
                int c0 = warpN0 + nt * 8 + lc;
                epi[c0 * EPI_LD + r0]           = acc[mt][nt][0];
                epi[(c0 + 1) * EPI_LD + r0]     = acc[mt][nt][1];
                epi[c0 * EPI_LD + r0 + 8]       = acc[mt][nt][2];
                epi[(c0 + 1) * EPI_LD + r0 + 8] = acc[mt][nt][3];
            }
        __syncthreads();
        write_tile(colBase, rowBase, true);
    }
}

// ---------------------------------------------------------------------------
// Persistent full GEMM: Y(BATCH x N_DIM) = Xh @ R, fp32 out.
// ---------------------------------------------------------------------------
__global__ __launch_bounds__(256, 2) void hgemm_yfull(
    const __half* __restrict__ A, const __half* __restrict__ B,
    float* __restrict__ Cf)
{
    extern __shared__ char smraw[];
    __half* smh = reinterpret_cast<__half*>(smraw);
    float*  smf = reinterpret_cast<float*>(smraw);
    const uint32_t smb = smem_u32(smraw);

    const int tid = threadIdx.x;
    const int warpId = tid >> 5;
    const int lid = tid & 31;
    const int warpM0 = (warpId >> 1) * 32;
    const int warpN0 = (warpId & 1) * 64;

    const int aRow0 = tid >> 2,          aCol0 = (tid & 3) << 3;
    const int aRow1 = (tid + 256) >> 2,  aCol1 = aCol0;
    const int bRow0 = tid >> 4,          bCol0 = (tid & 15) << 3;
    const int bRow1 = (tid >> 4) + 16,   bCol1 = bCol0;

    const uint32_t aFix = (uint32_t)(warpM0 + (lid & 15)) * (A_LD * 2)
                        + ((lid >> 4) << 3) * 2;
    const uint32_t bFix = (uint32_t)(lid & 15) * (B_LD * 2)
                        + (uint32_t)(warpN0 + ((lid >> 4) << 3)) * 2;
    const int lr = lid >> 2;
    const int lc = (lid & 3) << 1;

    for (int tile = blockIdx.x; tile < YTILES; tile += gridDim.x) {
        const int rowBase = (tile >> 4) * BM;
        const int colBase = (tile & 15) * BN;

        const __half* aP0 = A + (size_t)(rowBase + aRow0) * N_DIM + aCol0;
        const __half* aP1 = A + (size_t)(rowBase + aRow1) * N_DIM + aCol1;
        const __half* bP0 = B + (size_t)bRow0 * N_DIM + colBase + bCol0;
        const __half* bP1 = B + (size_t)bRow1 * N_DIM + colBase + bCol1;

        auto issue = [&](int step) {
            int buf = step % STAGES;
            size_t ka = (size_t)step * BK;
            __half* As = smh + buf * A_STG;
            __half* Bs = smh + B_BASE + buf * B_STG;
            __pipeline_memcpy_async(As + aRow0 * A_LD + aCol0, aP0 + ka, 16);
            __pipeline_memcpy_async(As + aRow1 * A_LD + aCol1, aP1 + ka, 16);
            __pipeline_memcpy_async(Bs + bRow0 * B_LD + bCol0, bP0 + ka * N_DIM, 16);
            __pipeline_memcpy_async(Bs + bRow1 * B_LD + bCol1, bP1 + ka * N_DIM, 16);
            __pipeline_commit();
        };

        float acc[2][8][4];
#pragma unroll
        for (int i = 0; i < 2; ++i)
#pragma unroll
            for (int j = 0; j < 8; ++j)
#pragma unroll
                for (int q = 0; q < 4; ++q) acc[i][j][q] = 0.0f;

        issue(0); issue(1); issue(2);

        for (int step = 0; step < NSTEPS; ++step) {
            if (step + 3 < NSTEPS) issue(step + 3);
            const int rem = NSTEPS - 1 - step;
            if (rem >= 3)      __pipeline_wait_prior(3);
            else if (rem == 2) __pipeline_wait_prior(2);
            else if (rem == 1) __pipeline_wait_prior(1);
            else               __pipeline_wait_prior(0);
            __syncthreads();

            const int buf = step % STAGES;
            const uint32_t aS = smb + buf * (A_STG * 2) + aFix;
            const uint32_t bS = smb + (B_BASE + buf * B_STG) * 2 + bFix;

#pragma unroll
            for (int kk = 0; kk < BK; kk += 16) {
                uint32_t ar[2][4], br[4][4];
                ldsm4(ar[0], aS + kk * 2);
                ldsm4(ar[1], aS + kk * 2 + 16 * (A_LD * 2));
#pragma unroll
                for (int nj = 0; nj < 4; ++nj)
                    ldsm4t(br[nj], bS + kk * (B_LD * 2) + nj * 32);
#pragma unroll
                for (int mt = 0; mt < 2; ++mt)
#pragma unroll
                    for (int nj = 0; nj < 4; ++nj) {
                        mma16816(acc[mt][nj * 2 + 0], ar[mt], br[nj]);
                        mma16816(acc[mt][nj * 2 + 1], ar[mt], br[nj] + 2);
                    }
            }
            __syncthreads();
        }

        // epilogue: stage fp32 tile, then coalesced float4 stores
#pragma unroll
        for (int mt = 0; mt < 2; ++mt)
#pragma unroll
            for (int nt = 0; nt < 8; ++nt) {
                int r0 = warpM0 + mt * 16 + lr;
                int c0 = warpN0 + nt * 8 + lc;
                smf[r0 * EPI_LD + c0]           = acc[mt][nt][0];
                smf[r0 * EPI_LD + c0 + 1]       = acc[mt][nt][1];
                smf[(r0 + 8) * EPI_LD + c0]     = acc[mt][nt][2];
                smf[(r0 + 8) * EPI_LD + c0 + 1] = acc[mt][nt][3];
            }
        __syncthreads();

#pragma unroll 4
        for (int g = 0; g < 16; ++g) {
            int e4 = tid + g * 256;
            int rr = e4 >> 5;
            int c4 = (e4 & 31) << 2;
            float4 v = *reinterpret_cast<const float4*>(smf + rr * EPI_LD + c4);
            size_t gi = (size_t)(rowBase + rr) * N_DIM + colBase + c4;
            *reinterpret_cast<float4*>(Cf + gi) = v;
        }
        __syncthreads();   // smem safe for next tile's cp.async
    }
}

extern "C" void kernel_launch(void* const* d_in, const int* in_sizes, int n_in,
                              void* d_out, int out_size) {
    const float* X      = (const float*)d_in[0];   // [BATCH, N]
    const float* S_flat = (const float*)d_in[1];   // [N*(N-1)/2]
    float* Y = (float*)d_out;                      // [BATCH, N]

    __half *S, *W, *P2, *P3, *P4, *E, *G, *R, *Xh;
    cudaGetSymbolAddress((void**)&S,  g_Sh);
    cudaGetSymbolAddress((void**)&W,  g_Wh);
    cudaGetSymbolAddress((void**)&P2, g_P2h);
    cudaGetSymbolAddress((void**)&P3, g_P3h);
    cudaGetSymbolAddress((void**)&P4, g_P4h);
    cudaGetSymbolAddress((void**)&E,  g_Eh);
    cudaGetSymbolAddress((void**)&G,  g_Gh);
    cudaGetSymbolAddress((void**)&R,  g_Rh);
    cudaGetSymbolAddress((void**)&Xh, g_Xh);

    cudaFuncSetAttribute(hgemm_tri,
                         cudaFuncAttributeMaxDynamicSharedMemorySize, SMEM_GEMM);
    cudaFuncSetAttribute(hgemm_yfull,
                         cudaFuncAttributeMaxDynamicSharedMemorySize, SMEM_GEMM);

    build_S_kernel<<<(N_DIM * N_DIM + 255) / 256, 256>>>(S_flat);
    convert_X_kernel<<<(BATCH * N_DIM / 4 + 255) / 256, 256>>>(X);

    // W = S @ S  (symmetric)
    hgemm_tri<<<NTRI, 256, SMEM_GEMM>>>(S, S, nullptr, W, nullptr,
                                        1.0f, 1.0f, nullptr, 0.0f);
    // P2 = W @ W  (symmetric)
    hgemm_tri<<<NTRI, 256, SMEM_GEMM>>>(W, W, nullptr, P2, nullptr,
                                        1.0f, 1.0f, nullptr, 0.0f);
    // merged: P3 = P2 @ W, P4 = P2 @ P2  (both symmetric)
    hgemm_tri<<<2 * NTRI, 256, SMEM_GEMM>>>(P2, W, P2, P3, P4,
                                            1.0f, 1.0f, nullptr, 0.0f);
    // E, G elementwise polynomials in W
    build_EG_kernel<<<(N_DIM * N_DIM / 2 + 255) / 256, 256>>>();
    // R = S @ G + E  (S@G antisymmetric -> msign = -1; E symmetric extra)
    hgemm_tri<<<NTRI, 256, SMEM_GEMM>>>(S, G, nullptr, R, nullptr,
                                        1.0f, -1.0f, E, 1.0f);
    // Y = X @ R  (persistent)
    hgemm_yfull<<<PERSIST_CTAS, 256, SMEM_GEMM>>>(Xh, R, Y);
}